// round 5
// baseline (speedup 1.0000x reference)
#include <cuda_runtime.h>
#include <cstdint>

#define TT   28
#define IND  28
#define HID  64
#define GG   256
#define EE   16
#define ES   20        // padded operand row stride (floats)
#define AS   (GG+8)
#define OUTD 10
#define NT   512
#define RPN  128       // row pairs
#define KQ0  23        // layer0 K-quarter (92/4)
#define KQ1  32        // layer1 K-quarter (128/4)

// Shared memory (floats):
//  h1seq [TT][HID][ES] = 35840
//  zbuf  [92][ES]      =  1840   (x rows 0..27, h0 rows 28..91)
//  hs    [HID][ES]     =  1280
//  act   [EE][AS]      =  4224
//  xch   12*128*4 u64  = 12288
//  wlin 640, blin 16
#define OFF_H1SEQ 0
#define OFF_ZBUF  (OFF_H1SEQ + TT*HID*ES)
#define OFF_HS    (OFF_ZBUF + 92*ES)
#define OFF_ACT   (OFF_HS + HID*ES)
#define OFF_XCH   (OFF_ACT + EE*AS)
#define OFF_WLIN  (OFF_XCH + 12*RPN*4*2)
#define OFF_BLIN  (OFF_WLIN + OUTD*HID)
#define SMEM_FLOATS (OFF_BLIN + 16)
#define SMEM_BYTES  (SMEM_FLOATS * 4)

typedef unsigned long long u64;

__device__ __forceinline__ u64 splat2(float w) {
    u64 r; asm("mov.b64 %0, {%1, %1};" : "=l"(r) : "f"(w)); return r;
}
__device__ __forceinline__ void ffma2(u64& d, u64 a, u64 b) {
    asm("fma.rn.f32x2 %0, %1, %2, %0;" : "+l"(d) : "l"(a), "l"(b));
}
__device__ __forceinline__ void fadd2(u64& d, u64 a) {
    asm("add.rn.f32x2 %0, %1, %0;" : "+l"(d) : "l"(a));
}
__device__ __forceinline__ float2 unpack2(u64 v) {
    float2 f; asm("mov.b64 {%0, %1}, %2;" : "=f"(f.x), "=f"(f.y) : "l"(v)); return f;
}
__device__ __forceinline__ float tanhfast(float x) {
    float r; asm("tanh.approx.f32 %0, %1;" : "=f"(r) : "f"(x)); return r;
}
__device__ __forceinline__ float sigfast(float x) {
    return fmaf(0.5f, tanhfast(0.5f * x), 0.5f);
}

// Partial gate GEMM: 2 rows, 16 batch elems, NK k-steps from contiguous rows.
template<int NK>
__device__ __forceinline__ void gate_partial(const float* __restrict__ base,
                                             const float* wr0, const float* wr1,
                                             u64 acc0[8], u64 acc1[8])
{
#pragma unroll
    for (int k = 0; k < NK; k++) {
        const ulonglong2* p = reinterpret_cast<const ulonglong2*>(base + k * ES);
        ulonglong2 q0 = p[0], q1 = p[1], q2 = p[2], q3 = p[3];
        u64 pw0 = splat2(wr0[k]);
        u64 pw1 = splat2(wr1[k]);
        ffma2(acc0[0], q0.x, pw0); ffma2(acc1[0], q0.x, pw1);
        ffma2(acc0[1], q0.y, pw0); ffma2(acc1[1], q0.y, pw1);
        ffma2(acc0[2], q1.x, pw0); ffma2(acc1[2], q1.x, pw1);
        ffma2(acc0[3], q1.y, pw0); ffma2(acc1[3], q1.y, pw1);
        ffma2(acc0[4], q2.x, pw0); ffma2(acc1[4], q2.x, pw1);
        ffma2(acc0[5], q2.y, pw0); ffma2(acc1[5], q2.y, pw1);
        ffma2(acc0[6], q3.x, pw0); ffma2(acc1[6], q3.x, pw1);
        ffma2(acc0[7], q3.y, pw0); ffma2(acc1[7], q3.y, pw1);
    }
}

// 4-way combine via smem exchange + activation + store into act[].
__device__ __forceinline__ void combine_activate(u64* xch, float* act,
                                                 u64 acc0[8], u64 acc1[8],
                                                 int rp, int kq, int j0, int gt,
                                                 float bias0, float bias1)
{
    // ship non-owned e-quarters
#pragma unroll
    for (int eqd = 0; eqd < 4; eqd++) {
        if (eqd != kq) {
            int pb = eqd * 3 + (kq > eqd ? kq - 1 : kq);
            ulonglong2* dst = reinterpret_cast<ulonglong2*>(xch + ((size_t)pb * RPN + rp) * 4);
            dst[0] = make_ulonglong2(acc0[2 * eqd], acc0[2 * eqd + 1]);
            dst[1] = make_ulonglong2(acc1[2 * eqd], acc1[2 * eqd + 1]);
        }
    }
    __syncthreads();

    u64 s0 = acc0[2 * kq], s1 = acc0[2 * kq + 1];
    u64 s2 = acc1[2 * kq], s3 = acc1[2 * kq + 1];
#pragma unroll
    for (int src = 0; src < 3; src++) {
        const ulonglong2* p = reinterpret_cast<const ulonglong2*>(xch + ((size_t)(kq * 3 + src) * RPN + rp) * 4);
        ulonglong2 a = p[0], b = p[1];
        fadd2(s0, a.x); fadd2(s1, a.y);
        fadd2(s2, b.x); fadd2(s3, b.y);
    }
    u64 pb0 = splat2(bias0), pb1 = splat2(bias1);
    fadd2(s0, pb0); fadd2(s1, pb0);
    fadd2(s2, pb1); fadd2(s3, pb1);

    float2 v0 = unpack2(s0), v1 = unpack2(s1);
    float2 v2 = unpack2(s2), v3 = unpack2(s3);
    float a00, a01, a02, a03, a10, a11, a12, a13;
    if (gt == 2) {
        a00 = tanhfast(v0.x); a01 = tanhfast(v0.y);
        a02 = tanhfast(v1.x); a03 = tanhfast(v1.y);
        a10 = tanhfast(v2.x); a11 = tanhfast(v2.y);
        a12 = tanhfast(v3.x); a13 = tanhfast(v3.y);
    } else {
        a00 = sigfast(v0.x); a01 = sigfast(v0.y);
        a02 = sigfast(v1.x); a03 = sigfast(v1.y);
        a10 = sigfast(v2.x); a11 = sigfast(v2.y);
        a12 = sigfast(v3.x); a13 = sigfast(v3.y);
    }
    int e = 4 * kq;
    *reinterpret_cast<float2*>(&act[(e + 0) * AS + j0]) = make_float2(a00, a10);
    *reinterpret_cast<float2*>(&act[(e + 1) * AS + j0]) = make_float2(a01, a11);
    *reinterpret_cast<float2*>(&act[(e + 2) * AS + j0]) = make_float2(a02, a12);
    *reinterpret_cast<float2*>(&act[(e + 3) * AS + j0]) = make_float2(a03, a13);
}

__global__ void __launch_bounds__(NT, 1)
rnn_fused_kernel(const float* __restrict__ x,
                 const float* __restrict__ Wih0, const float* __restrict__ Whh0,
                 const float* __restrict__ bih0, const float* __restrict__ bhh0,
                 const float* __restrict__ Wih1, const float* __restrict__ Whh1,
                 const float* __restrict__ bih1, const float* __restrict__ bhh1,
                 const float* __restrict__ Wlin, const float* __restrict__ blin,
                 float* __restrict__ out)
{
    extern __shared__ float sm[];
    float* h1seq = sm + OFF_H1SEQ;
    float* zbuf  = sm + OFF_ZBUF;          // x rows [0,28) + h0 rows [28,92)
    float* hs    = sm + OFF_HS;
    float* act   = sm + OFF_ACT;
    u64*   xch   = reinterpret_cast<u64*>(sm + OFF_XCH);
    float* wlin  = sm + OFF_WLIN;
    float* blin_s= sm + OFF_BLIN;

    const int tid = threadIdx.x;
    const int rp  = tid & (RPN - 1);       // row pair
    const int kq  = tid >> 7;              // K quarter (= owned e-quarter)
    const int j0  = 2 * rp;
    const int gt  = j0 >> 6;               // gate type (same for j0,j0+1)
    const int e0  = blockIdx.x * EE;
    const int unit = tid & 63;             // cell-update mapping
    const int eu   = tid >> 6;

    // init
    for (int idx = tid; idx < 92 * ES; idx += NT) zbuf[idx] = 0.0f;
    for (int idx = tid; idx < HID * ES; idx += NT) hs[idx] = 0.0f;
    for (int idx = tid; idx < OUTD * HID; idx += NT) wlin[idx] = Wlin[idx];
    if (tid < OUTD) blin_s[tid] = blin[tid];
    {   // stage x(t=0)
        int e = tid >> 5, k = tid & 31;
        if (e < EE && k < IND)
            zbuf[k * ES + e] = x[(size_t)(e0 + e) * (TT * IND) + k];
    }

    float c[2];
    c[0] = 0.0f; c[1] = 0.0f;

    // ================= Layer 0 =================
    {
        float w0[KQ0], w1[KQ0];
#pragma unroll
        for (int i = 0; i < KQ0; i++) {
            int r = kq * KQ0 + i;
            w0[i] = (r < IND) ? Wih0[j0 * IND + r] : Whh0[j0 * HID + (r - IND)];
            w1[i] = (r < IND) ? Wih0[(j0 + 1) * IND + r] : Whh0[(j0 + 1) * HID + (r - IND)];
        }
        const float bias0 = bih0[j0] + bhh0[j0];
        const float bias1 = bih0[j0 + 1] + bhh0[j0 + 1];
        const float* zbase = zbuf + kq * KQ0 * ES;

        __syncthreads();

#pragma unroll 1
        for (int t = 0; t < TT; t++) {
            u64 acc0[8], acc1[8];
#pragma unroll
            for (int i = 0; i < 8; i++) { acc0[i] = 0ULL; acc1[i] = 0ULL; }

            gate_partial<KQ0>(zbase, w0, w1, acc0, acc1);
            combine_activate(xch, act, acc0, acc1, rp, kq, j0, gt, bias0, bias1);
            __syncthreads();

            // cell update: 512 threads, 2 cells each; h0 -> zbuf rows 28.., h1seq
            float* h1t = h1seq + t * HID * ES;
#pragma unroll
            for (int q = 0; q < 2; q++) {
                int e = eu + q * 8;
                const float* ae = act + e * AS;
                float ig = ae[unit];
                float fg = ae[64 + unit];
                float gg = ae[128 + unit];
                float og = ae[192 + unit];
                c[q] = fg * c[q] + ig * gg;
                float h = og * tanhfast(c[q]);
                zbuf[(IND + unit) * ES + e] = h;
                h1t[unit * ES + e] = h;
            }
            if (t + 1 < TT) {
                int e = tid >> 5, k = tid & 31;
                if (e < EE && k < IND)
                    zbuf[k * ES + e] =
                        x[(size_t)(e0 + e) * (TT * IND) + (t + 1) * IND + k];
            }
            __syncthreads();
        }
    }

    // reset for layer 1
    c[0] = 0.0f; c[1] = 0.0f;
    for (int idx = tid; idx < HID * ES; idx += NT) hs[idx] = 0.0f;

    // ================= Layer 1 =================
    {
        // K=128: quarters 0,1 -> Wih1 (operand h1seq[t]); 2,3 -> Whh1 (operand hs)
        const int koff = (kq & 1) * KQ1;
        const float* Wsel = (kq < 2) ? Wih1 : Whh1;
        float w0[KQ1], w1[KQ1];
#pragma unroll
        for (int i = 0; i < KQ1; i++) {
            w0[i] = Wsel[j0 * HID + koff + i];
            w1[i] = Wsel[(j0 + 1) * HID + koff + i];
        }
        const float bias0 = bih1[j0] + bhh1[j0];
        const float bias1 = bih1[j0 + 1] + bhh1[j0 + 1];

        __syncthreads();

#pragma unroll 1
        for (int t = 0; t < TT; t++) {
            const float* base = (kq < 2) ? (h1seq + (t * HID + koff) * ES)
                                         : (hs + koff * ES);

            u64 acc0[8], acc1[8];
#pragma unroll
            for (int i = 0; i < 8; i++) { acc0[i] = 0ULL; acc1[i] = 0ULL; }

            gate_partial<KQ1>(base, w0, w1, acc0, acc1);
            combine_activate(xch, act, acc0, acc1, rp, kq, j0, gt, bias0, bias1);
            __syncthreads();

#pragma unroll
            for (int q = 0; q < 2; q++) {
                int e = eu + q * 8;
                const float* ae = act + e * AS;
                float ig = ae[unit];
                float fg = ae[64 + unit];
                float gg = ae[128 + unit];
                float og = ae[192 + unit];
                c[q] = fg * c[q] + ig * gg;
                float h = og * tanhfast(c[q]);
                hs[unit * ES + e] = h;
            }
            __syncthreads();
        }
    }

    // ================= Linear head =================
    if (tid < OUTD * EE) {
        int e = tid & (EE - 1);
        int o = tid >> 4;
        float s = blin_s[o];
#pragma unroll
        for (int k = 0; k < HID; k++)
            s += wlin[o * HID + k] * hs[k * ES + e];
        out[(size_t)(e0 + e) * OUTD + o] = s;
    }
}

extern "C" void kernel_launch(void* const* d_in, const int* in_sizes, int n_in,
                              void* d_out, int out_size)
{
    const float* x    = (const float*)d_in[0];
    const float* Wih0 = (const float*)d_in[1];
    const float* Whh0 = (const float*)d_in[2];
    const float* bih0 = (const float*)d_in[3];
    const float* bhh0 = (const float*)d_in[4];
    const float* Wih1 = (const float*)d_in[5];
    const float* Whh1 = (const float*)d_in[6];
    const float* bih1 = (const float*)d_in[7];
    const float* bhh1 = (const float*)d_in[8];
    const float* Wlin = (const float*)d_in[9];
    const float* blin = (const float*)d_in[10];
    float* out = (float*)d_out;

    int B = in_sizes[0] / (TT * IND);   // 16384
    int grid = B / EE;                  // 1024

    cudaFuncSetAttribute(rnn_fused_kernel,
                         cudaFuncAttributeMaxDynamicSharedMemorySize, SMEM_BYTES);
    rnn_fused_kernel<<<grid, NT, SMEM_BYTES>>>(
        x, Wih0, Whh0, bih0, bhh0, Wih1, Whh1, bih1, bhh1, Wlin, blin, out);
}

// round 6
// speedup vs baseline: 1.1619x; 1.1619x over previous
#include <cuda_runtime.h>
#include <cstdint>

#define TT   28
#define IND  28
#define HID  64
#define GG   256
#define EE   8         // batch elems per CTA
#define ES   12        // operand row stride (8 data + 4 pad floats), 48B -> 16B aligned
#define AS   (GG+8)
#define OUTD 10
#define NT   512
#define KQ0  23        // layer0 K-quarter (92/4)
#define KQ1  32        // layer1 K-quarter (128/4)

// Shared memory (floats):
//  h1seq [TT][HID][ES] = 21504
//  zbuf  [92][ES]      =  1104  (x rows 0..27, h0 rows 28..91)
//  hs    [HID][ES]     =   768
//  act   [EE][AS]      =  2112
//  xch   ulonglong2[12*128] = 6144 floats
//  wlin 640, blin 16
#define OFF_H1SEQ 0
#define OFF_ZBUF  (OFF_H1SEQ + TT*HID*ES)
#define OFF_HS    (OFF_ZBUF + 92*ES)
#define OFF_ACT   (OFF_HS + HID*ES)
#define OFF_XCH   (OFF_ACT + EE*AS)
#define OFF_WLIN  (OFF_XCH + 12*128*4)
#define OFF_BLIN  (OFF_WLIN + OUTD*HID)
#define SMEM_FLOATS (OFF_BLIN + 16)
#define SMEM_BYTES  (SMEM_FLOATS * 4)

typedef unsigned long long u64;

__device__ __forceinline__ u64 splat2(float w) {
    u64 r; asm("mov.b64 %0, {%1, %1};" : "=l"(r) : "f"(w)); return r;
}
__device__ __forceinline__ void ffma2(u64& d, u64 a, u64 b) {
    asm("fma.rn.f32x2 %0, %1, %2, %0;" : "+l"(d) : "l"(a), "l"(b));
}
__device__ __forceinline__ void fadd2(u64& d, u64 a) {
    asm("add.rn.f32x2 %0, %1, %0;" : "+l"(d) : "l"(a));
}
__device__ __forceinline__ float2 unpack2(u64 v) {
    float2 f; asm("mov.b64 {%0, %1}, %2;" : "=f"(f.x), "=f"(f.y) : "l"(v)); return f;
}
__device__ __forceinline__ float tanhfast(float x) {
    float r; asm("tanh.approx.f32 %0, %1;" : "=f"(r) : "f"(x)); return r;
}
__device__ __forceinline__ float sigfast(float x) {
    return fmaf(0.5f, tanhfast(0.5f * x), 0.5f);
}

// Gate partial: 2 gate rows (wA/wB), 8 batch elems, NK k-steps.
// Per k: 2 LDS.128 + 2 splat + 8 FFMA2.
template<int NK>
__device__ __forceinline__ void gate_partial(const float* __restrict__ base,
                                             const float* wA, const float* wB,
                                             u64 aA[4], u64 aB[4])
{
#pragma unroll
    for (int k = 0; k < NK; k++) {
        const ulonglong2* p = reinterpret_cast<const ulonglong2*>(base + k * ES);
        ulonglong2 q0 = p[0], q1 = p[1];         // 8 floats = 4 f32x2 pairs
        u64 wa = splat2(wA[k]);
        u64 wb = splat2(wB[k]);
        ffma2(aA[0], q0.x, wa); ffma2(aB[0], q0.x, wb);
        ffma2(aA[1], q0.y, wa); ffma2(aB[1], q0.y, wb);
        ffma2(aA[2], q1.x, wa); ffma2(aB[2], q1.x, wb);
        ffma2(aA[3], q1.y, wa); ffma2(aB[3], q1.y, wb);
    }
}

// 4-way K-combine via smem + activation + store act pairs.
__device__ __forceinline__ void combine_activate(ulonglong2* xch, float* act,
                                                 u64 aA[4], u64 aB[4],
                                                 int rp, int kq, int j0, int gt,
                                                 u64 biasA, u64 biasB)
{
#pragma unroll
    for (int q = 0; q < 4; q++) {
        if (q != kq) {
            int pb = q * 3 + (kq > q ? kq - 1 : kq);
            xch[pb * 128 + rp] = make_ulonglong2(aA[q], aB[q]);
        }
    }
    __syncthreads();

    u64 sA = aA[kq], sB = aB[kq];
#pragma unroll
    for (int s = 0; s < 3; s++) {
        ulonglong2 v = xch[(kq * 3 + s) * 128 + rp];
        fadd2(sA, v.x);
        fadd2(sB, v.y);
    }
    fadd2(sA, biasA);
    fadd2(sB, biasB);

    float2 vA = unpack2(sA), vB = unpack2(sB);
    float fA0, fA1, fB0, fB1;
    if (gt == 2) {
        fA0 = tanhfast(vA.x); fA1 = tanhfast(vA.y);
        fB0 = tanhfast(vB.x); fB1 = tanhfast(vB.y);
    } else {
        fA0 = sigfast(vA.x); fA1 = sigfast(vA.y);
        fB0 = sigfast(vB.x); fB1 = sigfast(vB.y);
    }
    int e = 2 * kq;
    *reinterpret_cast<float2*>(&act[e * AS + j0])       = make_float2(fA0, fB0);
    *reinterpret_cast<float2*>(&act[(e + 1) * AS + j0]) = make_float2(fA1, fB1);
}

__global__ void __launch_bounds__(NT, 1)
rnn_fused_kernel(const float* __restrict__ x,
                 const float* __restrict__ Wih0, const float* __restrict__ Whh0,
                 const float* __restrict__ bih0, const float* __restrict__ bhh0,
                 const float* __restrict__ Wih1, const float* __restrict__ Whh1,
                 const float* __restrict__ bih1, const float* __restrict__ bhh1,
                 const float* __restrict__ Wlin, const float* __restrict__ blin,
                 float* __restrict__ out)
{
    extern __shared__ float sm[];
    float* h1seq = sm + OFF_H1SEQ;
    float* zbuf  = sm + OFF_ZBUF;          // x rows [0,28) + h0 rows [28,92)
    float* hs    = sm + OFF_HS;
    float* act   = sm + OFF_ACT;
    ulonglong2* xch = reinterpret_cast<ulonglong2*>(sm + OFF_XCH);
    float* wlin  = sm + OFF_WLIN;
    float* blin_s= sm + OFF_BLIN;

    const int tid = threadIdx.x;
    const int rp  = tid & 127;             // row pair index
    const int kq  = tid >> 7;              // K quarter / owned e-pair
    const int j0  = 2 * rp;
    const int gt  = j0 >> 6;               // gate type (same for j0, j0+1)
    const int e0  = blockIdx.x * EE;
    const int unit = tid & 63;             // cell update: unit
    const int eu   = tid >> 6;             // cell update: batch elem (0..7)

    // init
    for (int idx = tid; idx < 92 * ES; idx += NT) zbuf[idx] = 0.0f;
    for (int idx = tid; idx < HID * ES; idx += NT) hs[idx] = 0.0f;
    for (int idx = tid; idx < OUTD * HID; idx += NT) wlin[idx] = Wlin[idx];
    if (tid < OUTD) blin_s[tid] = blin[tid];
    if (tid < 256) {   // stage x(t=0)
        int e = tid >> 5, k = tid & 31;
        if (k < IND)
            zbuf[k * ES + e] = x[(size_t)(e0 + e) * (TT * IND) + k];
    }

    float c = 0.0f;

    // ================= Layer 0 =================
    {
        float wA[KQ0], wB[KQ0];
#pragma unroll
        for (int i = 0; i < KQ0; i++) {
            int r = kq * KQ0 + i;
            wA[i] = (r < IND) ? Wih0[j0 * IND + r] : Whh0[j0 * HID + (r - IND)];
            wB[i] = (r < IND) ? Wih0[(j0 + 1) * IND + r] : Whh0[(j0 + 1) * HID + (r - IND)];
        }
        const u64 biasA = splat2(bih0[j0] + bhh0[j0]);
        const u64 biasB = splat2(bih0[j0 + 1] + bhh0[j0 + 1]);
        const float* zbase = zbuf + kq * KQ0 * ES;

        __syncthreads();

#pragma unroll 1
        for (int t = 0; t < TT; t++) {
            u64 aA[4], aB[4];
#pragma unroll
            for (int i = 0; i < 4; i++) { aA[i] = 0ULL; aB[i] = 0ULL; }

            gate_partial<KQ0>(zbase, wA, wB, aA, aB);
            combine_activate(xch, act, aA, aB, rp, kq, j0, gt, biasA, biasB);
            __syncthreads();

            // cell update: 512 threads, 1 cell each
            {
                const float* ae = act + eu * AS;
                float ig = ae[unit];
                float fg = ae[64 + unit];
                float gg = ae[128 + unit];
                float og = ae[192 + unit];
                c = fg * c + ig * gg;
                float h = og * tanhfast(c);
                zbuf[(IND + unit) * ES + eu] = h;
                h1seq[(t * HID + unit) * ES + eu] = h;
            }
            if (t + 1 < TT && tid < 256) {
                int e = tid >> 5, k = tid & 31;
                if (k < IND)
                    zbuf[k * ES + e] =
                        x[(size_t)(e0 + e) * (TT * IND) + (t + 1) * IND + k];
            }
            __syncthreads();
        }
    }

    // reset for layer 1
    c = 0.0f;
    for (int idx = tid; idx < HID * ES; idx += NT) hs[idx] = 0.0f;

    // ================= Layer 1 =================
    {
        // K=128: quarters 0,1 -> Wih1 (operand h1seq[t]); 2,3 -> Whh1 (operand hs)
        const int koff = (kq & 1) * KQ1;
        const float* Wsel = (kq < 2) ? Wih1 : Whh1;
        float wA[KQ1], wB[KQ1];
#pragma unroll
        for (int i = 0; i < KQ1; i++) {
            wA[i] = Wsel[j0 * HID + koff + i];
            wB[i] = Wsel[(j0 + 1) * HID + koff + i];
        }
        const u64 biasA = splat2(bih1[j0] + bhh1[j0]);
        const u64 biasB = splat2(bih1[j0 + 1] + bhh1[j0 + 1]);
        const float* hbase = hs + koff * ES;

        __syncthreads();

#pragma unroll 1
        for (int t = 0; t < TT; t++) {
            const float* base = (kq < 2) ? (h1seq + (t * HID + koff) * ES) : hbase;

            u64 aA[4], aB[4];
#pragma unroll
            for (int i = 0; i < 4; i++) { aA[i] = 0ULL; aB[i] = 0ULL; }

            gate_partial<KQ1>(base, wA, wB, aA, aB);
            combine_activate(xch, act, aA, aB, rp, kq, j0, gt, biasA, biasB);
            __syncthreads();

            {
                const float* ae = act + eu * AS;
                float ig = ae[unit];
                float fg = ae[64 + unit];
                float gg = ae[128 + unit];
                float og = ae[192 + unit];
                c = fg * c + ig * gg;
                float h = og * tanhfast(c);
                hs[unit * ES + eu] = h;
            }
            __syncthreads();
        }
    }

    // ================= Linear head =================
    if (tid < OUTD * EE) {
        int e = tid & (EE - 1);
        int o = tid >> 3;
        float s = blin_s[o];
#pragma unroll
        for (int k = 0; k < HID; k++)
            s += wlin[o * HID + k] * hs[k * ES + e];
        out[(size_t)(e0 + e) * OUTD + o] = s;
    }
}

extern "C" void kernel_launch(void* const* d_in, const int* in_sizes, int n_in,
                              void* d_out, int out_size)
{
    const float* x    = (const float*)d_in[0];
    const float* Wih0 = (const float*)d_in[1];
    const float* Whh0 = (const float*)d_in[2];
    const float* bih0 = (const float*)d_in[3];
    const float* bhh0 = (const float*)d_in[4];
    const float* Wih1 = (const float*)d_in[5];
    const float* Whh1 = (const float*)d_in[6];
    const float* bih1 = (const float*)d_in[7];
    const float* bhh1 = (const float*)d_in[8];
    const float* Wlin = (const float*)d_in[9];
    const float* blin = (const float*)d_in[10];
    float* out = (float*)d_out;

    int B = in_sizes[0] / (TT * IND);   // 16384
    int grid = B / EE;                  // 2048

    cudaFuncSetAttribute(rnn_fused_kernel,
                         cudaFuncAttributeMaxDynamicSharedMemorySize, SMEM_BYTES);
    rnn_fused_kernel<<<grid, NT, SMEM_BYTES>>>(
        x, Wih0, Whh0, bih0, bhh0, Wih1, Whh1, bih1, bhh1, Wlin, blin, out);
}